// round 5
// baseline (speedup 1.0000x reference)
#include <cuda_runtime.h>
#include <math.h>

// ---------------------------------------------------------------------------
// DeepJ biaxial LSTM.  B=1024, N=48, TU=256, NU=128, IN_T=50 (pad 64).
//   - time-axis LSTM layers: single step h=c=0 => feed-forward gate GEMMs
//     (Whh dead, f-gate dead).
//   - note-axis scan: sequential in n, independent per batch => persistent
//     blocks (128 blocks x 8 batches), weights streamed L2->smem per step.
//   - feats @ n_Wih0[:, :256].T hoisted to one big GEMM (g_xw).
//   - NEW: all inner loops use sm_103a packed fp32 FMA (fma.rn.f32x2),
//     pairing over k with row-major staged tiles => zero packing overhead.
// ---------------------------------------------------------------------------

#define BB 1024
#define NN 48
#define MM (BB * NN)   // 49152
#define K1 64          // IN_T=50 padded to 64

typedef unsigned long long u64;

// scratch (device globals: allocation-free)
__device__ float g_rnnin[MM * K1];
__device__ float g_w0p[1024 * K1];
__device__ float g_h1[MM * 256];
__device__ float g_feats[MM * 256];
__device__ float g_w2p[512 * 256];
__device__ float g_wc[512];
__device__ float g_xw[MM * 512];

__device__ __forceinline__ float sigf(float x) { return 1.0f / (1.0f + expf(-x)); }

// -------- packed fp32x2 helpers (sm_103a FFMA2) --------
__device__ __forceinline__ u64 ffma2(u64 a, u64 b, u64 c) {
    u64 d;
    asm("fma.rn.f32x2 %0, %1, %2, %3;" : "=l"(d) : "l"(a), "l"(b), "l"(c));
    return d;
}
__device__ __forceinline__ float fold2(u64 v) {   // lo + hi
    float x, y;
    asm("mov.b64 {%0, %1}, %2;" : "=f"(x), "=f"(y) : "l"(v));
    return x + y;
}
__device__ __forceinline__ u64 pack2(float x, float y) {
    u64 d;
    asm("mov.b64 %0, {%1, %2};" : "=l"(d) : "f"(x), "f"(y));
    return d;
}

// ------------------------------ prep kernels ------------------------------

__global__ void build_rnnin(const float* __restrict__ note) {
    int idx = blockIdx.x * blockDim.x + threadIdx.x;
    if (idx >= MM * K1) return;
    int f = idx & 63;
    int m = idx >> 6;
    int b = m / NN, n = m % NN;
    float v = 0.0f;
    if (f == 0) {
        v = (float)n * (1.0f / (float)NN);
    } else if (f < 13) {
        v = ((f - 1) == (n % 12)) ? 1.0f : 0.0f;
    } else if (f < 38) {
        int p = n + (f - 13) - 12;
        v = (p >= 0 && p < NN) ? note[b * NN + p] : 0.0f;
    } else if (f < 50) {
        const float* nb = note + b * NN + (f - 38) * 4;
        v = nb[0] + nb[1] + nb[2] + nb[3];
    }
    g_rnnin[idx] = v;
}

__global__ void pad_w0(const float* __restrict__ w) {  // (1024,50) -> (1024,64)
    int idx = blockIdx.x * blockDim.x + threadIdx.x;
    if (idx >= 1024 * K1) return;
    int k = idx & 63, r = idx >> 6;
    g_w0p[idx] = (k < 50) ? w[r * 50 + k] : 0.0f;
}

__global__ void prep_w2(const float* __restrict__ w) {  // n_Wih0 (512, 257)
    int idx = blockIdx.x * blockDim.x + threadIdx.x;
    if (idx >= 512 * 256) return;
    int k = idx & 255, r = idx >> 8;
    g_w2p[idx] = w[r * 257 + k];
    if (k == 0) g_wc[r] = w[r * 257 + 256];
}

// ------------------------- feed-forward gate GEMM -------------------------
// gates = X @ W.T (+bias).  ACT=true: 3 live gates -> h; ACT=false: 4 raw
// gate columns.  64 rows x 32 units per block, 256 threads, k-tiles of 16,
// double buffered row-major staging ([row][k], pad 20 => conflict-free
// LDS.128, 16B loads give k-pairs for FFMA2).

template <int U, bool ACT>
__global__ __launch_bounds__(256, 2)
void lstm_gemm(const float* __restrict__ X, int ldx, int KTOT,
               const float* __restrict__ W,
               const float* __restrict__ bias,
               float* __restrict__ out) {
    constexpr int NG = ACT ? 3 : 4;
    constexpr int NC = NG * 32;

    __shared__ __align__(16) float sX[2][64][20];
    __shared__ __align__(16) float sW[2][NC][20];

    const int t = threadIdx.x;
    const int tx = t & 15, ty = t >> 4;
    const int m0 = blockIdx.x * 64;
    const int u0 = blockIdx.y * 32;

    // X loader: 64 rows x 16 k = 256 float4, one per thread
    const int xm = t >> 2, xk = (t & 3) * 4;
    const float* Xp = X + (size_t)(m0 + xm) * ldx + xk;

    // W loader: NC rows x 4 float4 over <=2 slots per thread
    int wc_[2], wk_[2];
    bool wval[2];
    const float* Wp[2];
#pragma unroll
    for (int i = 0; i < 2; i++) {
        int lin = t + 256 * i;
        wval[i] = (lin < NC * 4);
        int c = lin >> 2;
        if (c >= NC) c = 0;
        int ks = (lin & 3) * 4;
        int gs = c >> 5;
        int ga = ACT ? ((gs == 0) ? 0 : gs + 1) : gs;  // {i,g,o} or {i,f,g,o}
        wc_[i] = c; wk_[i] = ks;
        Wp[i] = W + (size_t)(ga * U + u0 + (c & 31)) * KTOT + ks;
    }

    u64 acc[4][2][NG];
#pragma unroll
    for (int a = 0; a < 4; a++)
#pragma unroll
        for (int b = 0; b < 2; b++)
#pragma unroll
            for (int g = 0; g < NG; g++) acc[a][b][g] = 0ull;

    // prologue: tile 0 -> buffer 0
    float4 xr = *(const float4*)(Xp);
    float4 wr[2];
#pragma unroll
    for (int i = 0; i < 2; i++) if (wval[i]) wr[i] = *(const float4*)(Wp[i]);

    *(float4*)&sX[0][xm][xk] = xr;
#pragma unroll
    for (int i = 0; i < 2; i++)
        if (wval[i]) *(float4*)&sW[0][wc_[i]][wk_[i]] = wr[i];
    __syncthreads();

    const int nt = KTOT >> 4;
    for (int it = 0; it < nt; it++) {
        const int cb = it & 1;
        if (it + 1 < nt) {
            xr = *(const float4*)(Xp + (it + 1) * 16);
#pragma unroll
            for (int i = 0; i < 2; i++)
                if (wval[i]) wr[i] = *(const float4*)(Wp[i] + (it + 1) * 16);
        }
#pragma unroll
        for (int kq = 0; kq < 4; kq++) {
            ulonglong2 xd[4];
#pragma unroll
            for (int mm = 0; mm < 4; mm++)
                xd[mm] = *(const ulonglong2*)&sX[cb][ty * 4 + mm][kq * 4];
#pragma unroll
            for (int gs = 0; gs < NG; gs++)
#pragma unroll
                for (int uu = 0; uu < 2; uu++) {
                    ulonglong2 wd =
                        *(const ulonglong2*)&sW[cb][gs * 32 + uu * 16 + tx][kq * 4];
#pragma unroll
                    for (int mm = 0; mm < 4; mm++) {
                        acc[mm][uu][gs] = ffma2(xd[mm].x, wd.x, acc[mm][uu][gs]);
                        acc[mm][uu][gs] = ffma2(xd[mm].y, wd.y, acc[mm][uu][gs]);
                    }
                }
        }
        if (it + 1 < nt) {
            const int nb = (it + 1) & 1;
            *(float4*)&sX[nb][xm][xk] = xr;
#pragma unroll
            for (int i = 0; i < 2; i++)
                if (wval[i]) *(float4*)&sW[nb][wc_[i]][wk_[i]] = wr[i];
        }
        __syncthreads();
    }

    // epilogue
#pragma unroll
    for (int uu = 0; uu < 2; uu++) {
        const int ug = u0 + uu * 16 + tx;
        if constexpr (ACT) {
            float bi = bias[ug];
            float bg = bias[2 * U + ug];
            float bo = bias[3 * U + ug];
#pragma unroll
            for (int mm = 0; mm < 4; mm++) {
                float gi = fold2(acc[mm][uu][0]) + bi;
                float gg = fold2(acc[mm][uu][1]) + bg;
                float go = fold2(acc[mm][uu][2]) + bo;
                float cc = sigf(gi) * tanhf(gg);
                out[(size_t)(m0 + ty * 4 + mm) * U + ug] = sigf(go) * tanhf(cc);
            }
        } else {
#pragma unroll
            for (int gs = 0; gs < NG; gs++)
#pragma unroll
                for (int mm = 0; mm < 4; mm++)
                    out[(size_t)(m0 + ty * 4 + mm) * (4 * U) + gs * U + ug] =
                        fold2(acc[mm][uu][gs]);
        }
    }
}

// ------------------------------ note-axis scan -----------------------------
// 128 blocks x 8 batches, 256 threads.  Thread (u = t&127, gp = t>>7) owns
// gates {2gp, 2gp+1} of unit u for ALL 8 batches in the recurrent GEMMs
// (=> only 2 conflict-free weight loads + broadcast h loads per k-quad,
// FFMA2 over k-pairs).  Gates exchanged through sG for the pointwise stage,
// where thread (u, gp) owns batches 4gp..4gp+3.

__device__ __forceinline__ void load_wtile_regs(float4 pre[8],
                                                const float* __restrict__ W,
                                                int kt, int t) {
#pragma unroll
    for (int i = 0; i < 8; i++) {
        int lin = t + 256 * i;          // 512 rows x 4 float4
        int r = lin >> 2, k4 = lin & 3;
        pre[i] = *(const float4*)&W[r * 128 + kt + k4 * 4];
    }
}

__device__ __forceinline__ void sts_wtile(float* dst, const float4 pre[8], int t) {
#pragma unroll
    for (int i = 0; i < 8; i++) {
        int lin = t + 256 * i;
        int r = lin >> 2, k4 = lin & 3;
        *(float4*)&dst[r * 20 + k4 * 4] = pre[i];
    }
}

__device__ __forceinline__ void gemm_pass8(u64 acc[8][2],
                                           const float* __restrict__ W,
                                           const float* sH, float* sW,
                                           int t, int u, int gp) {
    const int r0 = (gp * 2 + 0) * 128 + u;
    const int r1 = (gp * 2 + 1) * 128 + u;
    float4 pre[8];
    load_wtile_regs(pre, W, 0, t);
    sts_wtile(sW, pre, t);
    __syncthreads();
    for (int it = 0; it < 8; it++) {
        const float* cur = sW + (it & 1) * 10240;
        if (it < 7) load_wtile_regs(pre, W, (it + 1) * 16, t);
#pragma unroll
        for (int kq = 0; kq < 4; kq++) {
            ulonglong2 wd0 = *(const ulonglong2*)&cur[r0 * 20 + kq * 4];
            ulonglong2 wd1 = *(const ulonglong2*)&cur[r1 * 20 + kq * 4];
#pragma unroll
            for (int b = 0; b < 8; b++) {
                ulonglong2 hd =
                    *(const ulonglong2*)&sH[b * 128 + it * 16 + kq * 4];
                acc[b][0] = ffma2(hd.x, wd0.x, acc[b][0]);
                acc[b][0] = ffma2(hd.y, wd0.y, acc[b][0]);
                acc[b][1] = ffma2(hd.x, wd1.x, acc[b][1]);
                acc[b][1] = ffma2(hd.y, wd1.y, acc[b][1]);
            }
        }
        if (it < 7) sts_wtile(sW + ((it + 1) & 1) * 10240, pre, t);
        __syncthreads();
    }
}

__global__ __launch_bounds__(256, 1)
void scan_kernel(const float* __restrict__ targets,
                 const float* __restrict__ Whh0,
                 const float* __restrict__ nb0,
                 const float* __restrict__ Wih1,
                 const float* __restrict__ Whh1,
                 const float* __restrict__ nb1,
                 const float* __restrict__ outW,
                 const float* __restrict__ outb,
                 float* __restrict__ out) {
    extern __shared__ float sh[];
    float* sW  = sh;               // 2 x 512 x 20 = 20480 floats
    float* sH1 = sh + 20480;       // 8 x 128
    float* sH2 = sH1 + 1024;       // 8 x 128
    float* sG  = sH2 + 1024;       // 8 x 512
    float* sWo = sG + 4096;        // 128

    const int t = threadIdx.x;
    const int u = t & 127, gp = t >> 7;
    const int B0 = blockIdx.x * 8;

    if (t < 128) sWo[t] = outW[t];
    for (int i = t; i < 2048; i += 256) sH1[i] = 0.0f;  // zeros sH1 + sH2

    float c1[4] = {0, 0, 0, 0}, c2[4] = {0, 0, 0, 0};
    float b0r[2], b1r[2], wcr[2];
#pragma unroll
    for (int g = 0; g < 2; g++) {
        int ga = gp * 2 + g;
        b0r[g] = nb0[ga * 128 + u];
        b1r[g] = nb1[ga * 128 + u];
        wcr[g] = g_wc[ga * 128 + u];
    }
    const float ob = outb[0];
    __syncthreads();

    for (int n = 0; n < NN; n++) {
        // ---- layer 0 ----
        u64 acc[8][2];
#pragma unroll
        for (int b = 0; b < 8; b++) {
            int bg = B0 + b;
            float cond = (n == 0) ? 0.0f : targets[bg * NN + n - 1];
            size_t m = (size_t)bg * NN + n;
#pragma unroll
            for (int g = 0; g < 2; g++) {
                int ga = gp * 2 + g;
                float v = g_xw[m * 512 + ga * 128 + u] + b0r[g] + cond * wcr[g];
                acc[b][g] = pack2(v, 0.0f);
            }
        }
        gemm_pass8(acc, Whh0, sH1, sW, t, u, gp);

#pragma unroll
        for (int b = 0; b < 8; b++)
#pragma unroll
            for (int g = 0; g < 2; g++)
                sG[b * 512 + (gp * 2 + g) * 128 + u] = fold2(acc[b][g]);
        __syncthreads();

#pragma unroll
        for (int j = 0; j < 4; j++) {
            int b = gp * 4 + j;
            float gi = sG[b * 512 + 0 * 128 + u];
            float gf = sG[b * 512 + 1 * 128 + u];
            float gg = sG[b * 512 + 2 * 128 + u];
            float go = sG[b * 512 + 3 * 128 + u];
            float cc = sigf(gf) * c1[j] + sigf(gi) * tanhf(gg);
            c1[j] = cc;
            sH1[b * 128 + u] = sigf(go) * tanhf(cc);
        }
        __syncthreads();

        // ---- layer 1 ----
        u64 acc2[8][2];
#pragma unroll
        for (int b = 0; b < 8; b++)
#pragma unroll
            for (int g = 0; g < 2; g++) acc2[b][g] = pack2(b1r[g], 0.0f);
        gemm_pass8(acc2, Wih1, sH1, sW, t, u, gp);
        gemm_pass8(acc2, Whh1, sH2, sW, t, u, gp);

#pragma unroll
        for (int b = 0; b < 8; b++)
#pragma unroll
            for (int g = 0; g < 2; g++)
                sG[b * 512 + (gp * 2 + g) * 128 + u] = fold2(acc2[b][g]);
        __syncthreads();

#pragma unroll
        for (int j = 0; j < 4; j++) {
            int b = gp * 4 + j;
            float gi = sG[b * 512 + 0 * 128 + u];
            float gf = sG[b * 512 + 1 * 128 + u];
            float gg = sG[b * 512 + 2 * 128 + u];
            float go = sG[b * 512 + 3 * 128 + u];
            float cc = sigf(gf) * c2[j] + sigf(gi) * tanhf(gg);
            c2[j] = cc;
            sH2[b * 128 + u] = sigf(go) * tanhf(cc);
        }
        __syncthreads();

        // ---- output: warp w handles batch w ----
        int w = t >> 5, lane = t & 31;
        float p = 0.0f;
#pragma unroll
        for (int j = 0; j < 4; j++)
            p += sH2[w * 128 + lane + 32 * j] * sWo[lane + 32 * j];
#pragma unroll
        for (int off = 16; off; off >>= 1)
            p += __shfl_down_sync(0xffffffffu, p, off);
        if (lane == 0) out[(B0 + w) * NN + n] = sigf(p + ob);
        // sH2 next rewritten only after layer-1 passes (internal barriers)
    }
}

// --------------------------------- launch ---------------------------------

extern "C" void kernel_launch(void* const* d_in, const int* in_sizes, int n_in,
                              void* d_out, int out_size) {
    (void)in_sizes; (void)n_in; (void)out_size;
    const float* note    = (const float*)d_in[0];
    const float* targets = (const float*)d_in[1];
    const float* tWih0   = (const float*)d_in[2];
    const float* tb0     = (const float*)d_in[4];
    const float* tWih1   = (const float*)d_in[5];
    const float* tb1     = (const float*)d_in[7];
    const float* nWih0   = (const float*)d_in[8];
    const float* nWhh0   = (const float*)d_in[9];
    const float* nb0     = (const float*)d_in[10];
    const float* nWih1   = (const float*)d_in[11];
    const float* nWhh1   = (const float*)d_in[12];
    const float* nb1     = (const float*)d_in[13];
    const float* outW    = (const float*)d_in[14];
    const float* outb    = (const float*)d_in[15];
    float* out = (float*)d_out;

    float *p_rnnin, *p_w0p, *p_h1, *p_feats, *p_w2p, *p_xw;
    cudaGetSymbolAddress((void**)&p_rnnin, g_rnnin);
    cudaGetSymbolAddress((void**)&p_w0p,   g_w0p);
    cudaGetSymbolAddress((void**)&p_h1,    g_h1);
    cudaGetSymbolAddress((void**)&p_feats, g_feats);
    cudaGetSymbolAddress((void**)&p_w2p,   g_w2p);
    cudaGetSymbolAddress((void**)&p_xw,    g_xw);

    build_rnnin<<<(MM * K1) / 256, 256>>>(note);
    pad_w0<<<(1024 * K1) / 256, 256>>>(tWih0);
    prep_w2<<<(512 * 256) / 256, 256>>>(nWih0);

    // h1 = act(rnn_in @ t_Wih0.T + b0)        (K padded to 64)
    lstm_gemm<256, true><<<dim3(768, 8), 256>>>(p_rnnin, K1, K1, p_w0p, tb0, p_h1);
    // feats = act(h1 @ t_Wih1.T + b1)
    lstm_gemm<256, true><<<dim3(768, 8), 256>>>(p_h1, 256, 256, tWih1, tb1, p_feats);
    // xw = feats @ n_Wih0[:, :256].T          (raw gates, bias added in scan)
    lstm_gemm<128, false><<<dim3(768, 4), 256>>>(p_feats, 256, 256, p_w2p, nullptr, p_xw);

    const int smem = 26752 * (int)sizeof(float);  // 107008 B
    cudaFuncSetAttribute(scan_kernel, cudaFuncAttributeMaxDynamicSharedMemorySize, smem);
    scan_kernel<<<128, 256, smem>>>(targets, nWhh0, nb0, nWih1, nWhh1, nb1,
                                    outW, outb, out);
}

// round 6
// speedup vs baseline: 1.1666x; 1.1666x over previous
#include <cuda_runtime.h>
#include <math.h>

// ---------------------------------------------------------------------------
// DeepJ biaxial LSTM.  B=1024, N=48, TU=256, NU=128, IN_T=50 (pad 64).
//   - time-axis LSTM layers: single step h=c=0 => feed-forward gate GEMMs
//     (Whh dead, f-gate dead).
//   - NEW: the three feed-forward GEMMs run on tensor cores
//     (mma.sync m16n8k8 tf32) with 3xTF32 hi/lo splitting => ~fp32 accuracy.
//     Weights pre-interleaved (i,g,o per unit adjacent) so activation fuses
//     in the GEMM epilogue via a smem tile dump.
//   - note-axis scan: persistent blocks (128 x 8 batches), scalar fp32
//     (restored R3 version; FFMA2 experiment reverted).
// ---------------------------------------------------------------------------

#define BB 1024
#define NN 48
#define MM (BB * NN)   // 49152
#define K1 64          // IN_T=50 padded to 64

// scratch (device globals: allocation-free)
__device__ float g_rnnin[MM * K1];
__device__ float g_w0p[1024 * K1];     // padded t_Wih0
__device__ float g_w0i[768 * K1];      // interleaved 3-gate t_Wih0
__device__ float g_w1i[768 * 256];     // interleaved 3-gate t_Wih1
__device__ float g_h1[MM * 256];
__device__ float g_feats[MM * 256];
__device__ float g_w2p[512 * 256];     // n_Wih0[:, :256]
__device__ float g_wc[512];            // n_Wih0[:, 256] (cond column)
__device__ float g_xw[MM * 512];

__device__ __forceinline__ float sigf(float x) { return 1.0f / (1.0f + expf(-x)); }

__device__ __forceinline__ unsigned tf32r(float x) {
    unsigned r;
    asm("cvt.rna.tf32.f32 %0, %1;" : "=r"(r) : "f"(x));
    return r;
}

__device__ __forceinline__ void mma8(float c[4], const unsigned a[4],
                                     const unsigned b[2]) {
    asm volatile(
        "mma.sync.aligned.m16n8k8.row.col.f32.tf32.tf32.f32 "
        "{%0,%1,%2,%3}, {%4,%5,%6,%7}, {%8,%9}, {%0,%1,%2,%3};"
        : "+f"(c[0]), "+f"(c[1]), "+f"(c[2]), "+f"(c[3])
        : "r"(a[0]), "r"(a[1]), "r"(a[2]), "r"(a[3]), "r"(b[0]), "r"(b[1]));
}

// ------------------------------ prep kernels ------------------------------

__global__ void build_rnnin(const float* __restrict__ note) {
    int idx = blockIdx.x * blockDim.x + threadIdx.x;
    if (idx >= MM * K1) return;
    int f = idx & 63;
    int m = idx >> 6;
    int b = m / NN, n = m % NN;
    float v = 0.0f;
    if (f == 0) {
        v = (float)n * (1.0f / (float)NN);
    } else if (f < 13) {
        v = ((f - 1) == (n % 12)) ? 1.0f : 0.0f;
    } else if (f < 38) {
        int p = n + (f - 13) - 12;
        v = (p >= 0 && p < NN) ? note[b * NN + p] : 0.0f;
    } else if (f < 50) {
        const float* nb = note + b * NN + (f - 38) * 4;
        v = nb[0] + nb[1] + nb[2] + nb[3];
    }
    g_rnnin[idx] = v;
}

__global__ void pad_w0(const float* __restrict__ w) {  // (1024,50) -> (1024,64)
    int idx = blockIdx.x * blockDim.x + threadIdx.x;
    if (idx >= 1024 * K1) return;
    int k = idx & 63, r = idx >> 6;
    g_w0p[idx] = (k < 50) ? w[r * 50 + k] : 0.0f;
}

__global__ void prep_w2(const float* __restrict__ w) {  // n_Wih0 (512, 257)
    int idx = blockIdx.x * blockDim.x + threadIdx.x;
    if (idx >= 512 * 256) return;
    int k = idx & 255, r = idx >> 8;
    g_w2p[idx] = w[r * 257 + k];
    if (k == 0) g_wc[r] = w[r * 257 + 256];
}

// Interleave live gates: dst row c = 3u+g3, g3 in {i,g,o} = orig gates {0,2,3}
__global__ void prep_wi(const float* __restrict__ w, int K,
                        float* __restrict__ dst) {
    int idx = blockIdx.x * blockDim.x + threadIdx.x;
    if (idx >= 768 * K) return;
    int k = idx % K, c = idx / K;
    int u = c / 3, g3 = c - 3 * u;
    int ga = (g3 == 0) ? 0 : (g3 + 1);
    dst[idx] = w[(size_t)(ga * 256 + u) * K + k];
}

// ----------------------- tf32 tensor-core gate GEMM -----------------------
// out = X[M x K] @ W[C x K]^T.  3xTF32 split for ~fp32 accuracy.
// Block tile 128 x NT, 8 warps (4 m x 2 n).  K chunks of 32 staged hi/lo in
// shared (row stride 36 => conflict-free fragment loads).
// ACT=true : NT=96 = 32 units x (i,g,o);  epilogue computes h and stores
//            out[m, unit] (ldo = 256 units total, 32 per block).
// ACT=false: NT=64 raw gate columns, stored to out[m, c0+c] (ldo=512).

template <int NT, int NI, bool ACT>
__global__ __launch_bounds__(256, 2)
void mma_gemm(const float* __restrict__ X, int K,
              const float* __restrict__ W,
              const float* __restrict__ bias,
              float* __restrict__ out, int ldo) {
    extern __shared__ float sh[];
    float* sAh = sh;
    float* sAl = sAh + 128 * 36;
    float* sBh = sAl + 128 * 36;
    float* sBl = sBh + NT * 36;

    const int t = threadIdx.x;
    const int lane = t & 31, wid = t >> 5;
    const int wm = wid & 3, wn = wid >> 2;
    const int gid = lane >> 2, tid4 = lane & 3;
    const int m0 = blockIdx.x * 128;
    const int c0 = blockIdx.y * NT;

    float acc[2][NI][4];
#pragma unroll
    for (int mi = 0; mi < 2; mi++)
#pragma unroll
        for (int ni = 0; ni < NI; ni++)
#pragma unroll
            for (int q = 0; q < 4; q++) acc[mi][ni][q] = 0.0f;

    const int nchunks = K >> 5;
    for (int kc = 0; kc < nchunks; kc++) {
        __syncthreads();
        // stage A (128 x 32): 4 float4 per thread
#pragma unroll
        for (int j = 0; j < 4; j++) {
            int i = t + 256 * j;
            int r = i >> 3, c4 = (i & 7) * 4;
            float4 v = *(const float4*)&X[(size_t)(m0 + r) * K + kc * 32 + c4];
            float4 h, l;
            h.x = __uint_as_float(tf32r(v.x)); l.x = __uint_as_float(tf32r(v.x - h.x));
            h.y = __uint_as_float(tf32r(v.y)); l.y = __uint_as_float(tf32r(v.y - h.y));
            h.z = __uint_as_float(tf32r(v.z)); l.z = __uint_as_float(tf32r(v.z - h.z));
            h.w = __uint_as_float(tf32r(v.w)); l.w = __uint_as_float(tf32r(v.w - h.w));
            *(float4*)&sAh[r * 36 + c4] = h;
            *(float4*)&sAl[r * 36 + c4] = l;
        }
        // stage B (NT x 32): NT/32 float4 per thread
#pragma unroll
        for (int j = 0; j < NT / 32; j++) {
            int i = t + 256 * j;
            int r = i >> 3, c4 = (i & 7) * 4;
            float4 v = *(const float4*)&W[(size_t)(c0 + r) * K + kc * 32 + c4];
            float4 h, l;
            h.x = __uint_as_float(tf32r(v.x)); l.x = __uint_as_float(tf32r(v.x - h.x));
            h.y = __uint_as_float(tf32r(v.y)); l.y = __uint_as_float(tf32r(v.y - h.y));
            h.z = __uint_as_float(tf32r(v.z)); l.z = __uint_as_float(tf32r(v.z - h.z));
            h.w = __uint_as_float(tf32r(v.w)); l.w = __uint_as_float(tf32r(v.w - h.w));
            *(float4*)&sBh[r * 36 + c4] = h;
            *(float4*)&sBl[r * 36 + c4] = l;
        }
        __syncthreads();

#pragma unroll
        for (int kk = 0; kk < 4; kk++) {
            const int kb = kk * 8;
            unsigned Ah[2][4], Al[2][4], Bh[NI][2], Bl[NI][2];
#pragma unroll
            for (int mi = 0; mi < 2; mi++) {
                int r = wm * 32 + mi * 16 + gid;
                Ah[mi][0] = __float_as_uint(sAh[r * 36 + kb + tid4]);
                Ah[mi][1] = __float_as_uint(sAh[(r + 8) * 36 + kb + tid4]);
                Ah[mi][2] = __float_as_uint(sAh[r * 36 + kb + tid4 + 4]);
                Ah[mi][3] = __float_as_uint(sAh[(r + 8) * 36 + kb + tid4 + 4]);
                Al[mi][0] = __float_as_uint(sAl[r * 36 + kb + tid4]);
                Al[mi][1] = __float_as_uint(sAl[(r + 8) * 36 + kb + tid4]);
                Al[mi][2] = __float_as_uint(sAl[r * 36 + kb + tid4 + 4]);
                Al[mi][3] = __float_as_uint(sAl[(r + 8) * 36 + kb + tid4 + 4]);
            }
#pragma unroll
            for (int ni = 0; ni < NI; ni++) {
                int c = wn * (NT / 2) + ni * 8 + gid;
                Bh[ni][0] = __float_as_uint(sBh[c * 36 + kb + tid4]);
                Bh[ni][1] = __float_as_uint(sBh[c * 36 + kb + tid4 + 4]);
                Bl[ni][0] = __float_as_uint(sBl[c * 36 + kb + tid4]);
                Bl[ni][1] = __float_as_uint(sBl[c * 36 + kb + tid4 + 4]);
            }
#pragma unroll
            for (int mi = 0; mi < 2; mi++)
#pragma unroll
                for (int ni = 0; ni < NI; ni++) {
                    mma8(acc[mi][ni], Ah[mi], Bh[ni]);
                    mma8(acc[mi][ni], Al[mi], Bh[ni]);
                    mma8(acc[mi][ni], Ah[mi], Bl[ni]);
                }
        }
    }

    // dump accumulators to smem tile [128][NT+4]
    __syncthreads();
    const int NTS = NT + 4;
#pragma unroll
    for (int mi = 0; mi < 2; mi++)
#pragma unroll
        for (int ni = 0; ni < NI; ni++) {
            int r = wm * 32 + mi * 16 + gid;
            int c = wn * (NT / 2) + ni * 8 + tid4 * 2;
            sh[r * NTS + c]           = acc[mi][ni][0];
            sh[r * NTS + c + 1]       = acc[mi][ni][1];
            sh[(r + 8) * NTS + c]     = acc[mi][ni][2];
            sh[(r + 8) * NTS + c + 1] = acc[mi][ni][3];
        }
    __syncthreads();

    if constexpr (ACT) {
        const int ul = t & 31, mr = t >> 5;
        const int ug = blockIdx.y * 32 + ul;      // global unit
        const float bi = bias[ug];
        const float bg = bias[2 * 256 + ug];
        const float bo = bias[3 * 256 + ug];
#pragma unroll
        for (int j = 0; j < 16; j++) {
            int m = mr + j * 8;
            float gi = sh[m * NTS + ul * 3 + 0] + bi;
            float gg = sh[m * NTS + ul * 3 + 1] + bg;
            float go = sh[m * NTS + ul * 3 + 2] + bo;
            float cc = sigf(gi) * tanhf(gg);
            out[(size_t)(m0 + m) * ldo + ug] = sigf(go) * tanhf(cc);
        }
    } else {
        const int cl = t & 63, mr = t >> 6;
#pragma unroll
        for (int j = 0; j < 32; j++) {
            int m = mr + j * 4;
            out[(size_t)(m0 + m) * ldo + c0 + cl] = sh[m * NTS + cl];
        }
    }
}

// ------------------------------ note-axis scan -----------------------------
// (restored R3 version)  128 blocks x 8 batches, 256 threads.  Thread owns
// unit u = t&127 for batches (t>>7)*4 .. +3.  Weights staged per 16-k tile
// into double-buffered shared (pad-20 stride => conflict-free LDS.128).

__device__ __forceinline__ void load_wtile_regs(float4 pre[8],
                                                const float* __restrict__ W,
                                                int kt, int t) {
#pragma unroll
    for (int i = 0; i < 8; i++) {
        int lin = t + 256 * i;          // 512 rows x 4 float4
        int r = lin >> 2, k4 = lin & 3;
        pre[i] = *(const float4*)&W[r * 128 + kt + k4 * 4];
    }
}

__device__ __forceinline__ void sts_wtile(float* dst, const float4 pre[8], int t) {
#pragma unroll
    for (int i = 0; i < 8; i++) {
        int lin = t + 256 * i;
        int r = lin >> 2, k4 = lin & 3;
        *(float4*)&dst[r * 20 + k4 * 4] = pre[i];
    }
}

__device__ __forceinline__ void accum_tile(float acc[4][4], const float* sWt,
                                           const float* sH, int kt, int u, int bp) {
#pragma unroll
    for (int kk = 0; kk < 16; kk += 4) {
        float4 wv[4];
#pragma unroll
        for (int g = 0; g < 4; g++)
            wv[g] = *(const float4*)&sWt[(g * 128 + u) * 20 + kk];
#pragma unroll
        for (int b = 0; b < 4; b++) {
            float4 hv = *(const float4*)&sH[(bp * 4 + b) * 128 + kt + kk];
#pragma unroll
            for (int g = 0; g < 4; g++) {
                acc[b][g] += hv.x * wv[g].x;
                acc[b][g] += hv.y * wv[g].y;
                acc[b][g] += hv.z * wv[g].z;
                acc[b][g] += hv.w * wv[g].w;
            }
        }
    }
}

__device__ __forceinline__ void gemm_pass(float acc[4][4],
                                          const float* __restrict__ W,
                                          const float* sH, float* sW,
                                          int t, int u, int bp) {
    float4 pre[8];
    load_wtile_regs(pre, W, 0, t);
    sts_wtile(sW, pre, t);
    __syncthreads();
    for (int it = 0; it < 8; it++) {
        float* cur = sW + (it & 1) * 10240;
        if (it < 7) load_wtile_regs(pre, W, (it + 1) * 16, t);
        accum_tile(acc, cur, sH, it * 16, u, bp);
        if (it < 7) sts_wtile(sW + ((it + 1) & 1) * 10240, pre, t);
        __syncthreads();
    }
}

__global__ __launch_bounds__(256, 1)
void scan_kernel(const float* __restrict__ targets,
                 const float* __restrict__ Whh0,
                 const float* __restrict__ nb0,
                 const float* __restrict__ Wih1,
                 const float* __restrict__ Whh1,
                 const float* __restrict__ nb1,
                 const float* __restrict__ outW,
                 const float* __restrict__ outb,
                 float* __restrict__ out) {
    extern __shared__ float sh[];
    float* sW  = sh;              // 2 x 512 x 20 = 20480
    float* sH1 = sh + 20480;      // 8 x 128
    float* sH2 = sH1 + 1024;      // 8 x 128
    float* sWo = sH2 + 1024;      // 128

    const int t = threadIdx.x;
    const int u = t & 127, bp = t >> 7;
    const int B0 = blockIdx.x * 8;

    if (t < 128) sWo[t] = outW[t];
    for (int i = t; i < 2048; i += 256) sH1[i] = 0.0f;  // zeros sH1+sH2

    float c1[4] = {0, 0, 0, 0}, c2[4] = {0, 0, 0, 0};
    float b0r[4], b1r[4], wcr[4];
#pragma unroll
    for (int g = 0; g < 4; g++) {
        b0r[g] = nb0[g * 128 + u];
        b1r[g] = nb1[g * 128 + u];
        wcr[g] = g_wc[g * 128 + u];
    }
    const float ob = outb[0];
    __syncthreads();

    for (int n = 0; n < NN; n++) {
        // ---- layer 0 ----
        float acc[4][4];
#pragma unroll
        for (int b = 0; b < 4; b++) {
            int bg = B0 + bp * 4 + b;
            float cond = (n == 0) ? 0.0f : targets[bg * NN + n - 1];
            size_t m = (size_t)bg * NN + n;
#pragma unroll
            for (int g = 0; g < 4; g++)
                acc[b][g] = g_xw[m * 512 + g * 128 + u] + b0r[g] + cond * wcr[g];
        }
        gemm_pass(acc, Whh0, sH1, sW, t, u, bp);

        float h1n[4];
#pragma unroll
        for (int b = 0; b < 4; b++) {
            float cc = sigf(acc[b][1]) * c1[b] + sigf(acc[b][0]) * tanhf(acc[b][2]);
            c1[b] = cc;
            h1n[b] = sigf(acc[b][3]) * tanhf(cc);
        }
#pragma unroll
        for (int b = 0; b < 4; b++) sH1[(bp * 4 + b) * 128 + u] = h1n[b];
        __syncthreads();

        // ---- layer 1 ----
        float acc2[4][4];
#pragma unroll
        for (int b = 0; b < 4; b++)
#pragma unroll
            for (int g = 0; g < 4; g++) acc2[b][g] = b1r[g];
        gemm_pass(acc2, Wih1, sH1, sW, t, u, bp);
        gemm_pass(acc2, Whh1, sH2, sW, t, u, bp);

        float h2n[4];
#pragma unroll
        for (int b = 0; b < 4; b++) {
            float cc = sigf(acc2[b][1]) * c2[b] + sigf(acc2[b][0]) * tanhf(acc2[b][2]);
            c2[b] = cc;
            h2n[b] = sigf(acc2[b][3]) * tanhf(cc);
        }
#pragma unroll
        for (int b = 0; b < 4; b++) sH2[(bp * 4 + b) * 128 + u] = h2n[b];
        __syncthreads();

        // ---- output: warp w handles batch w ----
        int w = t >> 5, lane = t & 31;
        float p = 0.0f;
#pragma unroll
        for (int j = 0; j < 4; j++)
            p += sH2[w * 128 + lane + 32 * j] * sWo[lane + 32 * j];
#pragma unroll
        for (int off = 16; off; off >>= 1)
            p += __shfl_down_sync(0xffffffffu, p, off);
        if (lane == 0) out[(B0 + w) * NN + n] = sigf(p + ob);
    }
}

// --------------------------------- launch ---------------------------------

extern "C" void kernel_launch(void* const* d_in, const int* in_sizes, int n_in,
                              void* d_out, int out_size) {
    (void)in_sizes; (void)n_in; (void)out_size;
    const float* note    = (const float*)d_in[0];
    const float* targets = (const float*)d_in[1];
    const float* tWih0   = (const float*)d_in[2];
    const float* tb0     = (const float*)d_in[4];
    const float* tWih1   = (const float*)d_in[5];
    const float* tb1     = (const float*)d_in[7];
    const float* nWih0   = (const float*)d_in[8];
    const float* nWhh0   = (const float*)d_in[9];
    const float* nb0     = (const float*)d_in[10];
    const float* nWih1   = (const float*)d_in[11];
    const float* nWhh1   = (const float*)d_in[12];
    const float* nb1     = (const float*)d_in[13];
    const float* outW    = (const float*)d_in[14];
    const float* outb    = (const float*)d_in[15];
    float* out = (float*)d_out;

    float *p_rnnin, *p_w0p, *p_w0i, *p_w1i, *p_h1, *p_feats, *p_w2p, *p_xw;
    cudaGetSymbolAddress((void**)&p_rnnin, g_rnnin);
    cudaGetSymbolAddress((void**)&p_w0p,   g_w0p);
    cudaGetSymbolAddress((void**)&p_w0i,   g_w0i);
    cudaGetSymbolAddress((void**)&p_w1i,   g_w1i);
    cudaGetSymbolAddress((void**)&p_h1,    g_h1);
    cudaGetSymbolAddress((void**)&p_feats, g_feats);
    cudaGetSymbolAddress((void**)&p_w2p,   g_w2p);
    cudaGetSymbolAddress((void**)&p_xw,    g_xw);

    build_rnnin<<<(MM * K1) / 256, 256>>>(note);
    pad_w0<<<(1024 * K1) / 256, 256>>>(tWih0);
    prep_w2<<<(512 * 256) / 256, 256>>>(nWih0);
    prep_wi<<<(768 * K1 + 255) / 256, 256>>>(p_w0p, K1, p_w0i);
    prep_wi<<<(768 * 256 + 255) / 256, 256>>>(tWih1, 256, p_w1i);

    const int smemA = (128 * 36 * 2 + 96 * 36 * 2) * (int)sizeof(float); // 64512
    const int smemB = (128 * 36 * 2 + 64 * 36 * 2) * (int)sizeof(float); // 55296
    cudaFuncSetAttribute((const void*)mma_gemm<96, 6, true>,
                         cudaFuncAttributeMaxDynamicSharedMemorySize, smemA);
    cudaFuncSetAttribute((const void*)mma_gemm<64, 4, false>,
                         cudaFuncAttributeMaxDynamicSharedMemorySize, smemB);

    // h1 = act(rnn_in @ t_Wih0.T + b0)        (K padded to 64)
    mma_gemm<96, 6, true><<<dim3(384, 8), 256, smemA>>>(p_rnnin, K1, p_w0i,
                                                        tb0, p_h1, 256);
    // feats = act(h1 @ t_Wih1.T + b1)
    mma_gemm<96, 6, true><<<dim3(384, 8), 256, smemA>>>(p_h1, 256, p_w1i,
                                                        tb1, p_feats, 256);
    // xw = feats @ n_Wih0[:, :256].T          (raw gates, bias added in scan)
    mma_gemm<64, 4, false><<<dim3(384, 8), 256, smemB>>>(p_feats, 256, p_w2p,
                                                         nullptr, p_xw, 512);

    const int smemS = 22656 * (int)sizeof(float);  // 90624 B
    cudaFuncSetAttribute(scan_kernel, cudaFuncAttributeMaxDynamicSharedMemorySize, smemS);
    scan_kernel<<<128, 256, smemS>>>(targets, nWhh0, nb0, nWih1, nWhh1, nb1,
                                     outW, outb, out);
}